// round 2
// baseline (speedup 1.0000x reference)
#include <cuda_runtime.h>

#define NN 1024
#define BB 8
#define DIN 64
#define DOUT 64
#define EMB 16
#define DPE 16
#define KIO 8192   // 2*64*64

// ---- device scratch (no allocations allowed) ----
__device__ float g_sim[NN * NN];          // 4 MB
__device__ float g_w[NN * KIO];           // 32 MB  weights[n][k][i][o]
__device__ float g_bias[NN * DOUT];       // 256 KB
__device__ float g_e[BB * NN * NN];       // 32 MB  exp(-d1), symmetric per b
__device__ float g_Sinv[BB * NN];         // 32 KB
__device__ float g_sxT[NN * BB * DIN];    // 2 MB   sx as [m][b][d]
__device__ float g_s1[NN * BB * DIN];     // 2 MB   sim@sx as [n][b][d]

// ---------------------------------------------------------------------------
// K0: sim = softmax(relu(E E^T), axis=1)   one block per row
// ---------------------------------------------------------------------------
__global__ __launch_bounds__(256) void sim_kernel(const float* __restrict__ E) {
    const int i = blockIdx.x;
    const int t = threadIdx.x;
    __shared__ float Ei[EMB];
    __shared__ float red[256];
    if (t < EMB) Ei[t] = E[i * EMB + t];
    __syncthreads();

    float v[4];
    float mx = -1e30f;
#pragma unroll
    for (int r = 0; r < 4; r++) {
        int j = t + r * 256;
        const float4* Ej = reinterpret_cast<const float4*>(E + j * EMB);
        float acc = 0.f;
#pragma unroll
        for (int q = 0; q < 4; q++) {
            float4 e4 = Ej[q];
            acc += Ei[q * 4 + 0] * e4.x + Ei[q * 4 + 1] * e4.y
                 + Ei[q * 4 + 2] * e4.z + Ei[q * 4 + 3] * e4.w;
        }
        acc = fmaxf(acc, 0.f);
        v[r] = acc;
        mx = fmaxf(mx, acc);
    }
    red[t] = mx; __syncthreads();
    for (int s = 128; s > 0; s >>= 1) { if (t < s) red[t] = fmaxf(red[t], red[t + s]); __syncthreads(); }
    mx = red[0]; __syncthreads();

    float sum = 0.f;
#pragma unroll
    for (int r = 0; r < 4; r++) { v[r] = __expf(v[r] - mx); sum += v[r]; }
    red[t] = sum; __syncthreads();
    for (int s = 128; s > 0; s >>= 1) { if (t < s) red[t] += red[t + s]; __syncthreads(); }
    float inv = 1.0f / red[0];
#pragma unroll
    for (int r = 0; r < 4; r++) g_sim[i * NN + t + r * 256] = v[r] * inv;
}

// ---------------------------------------------------------------------------
// K1: weights[n, kio] = sum_d E[n,d] * Wp[d, kio]
// grid (32 kio-tiles of 256, 8 n-chunks of 128)
// ---------------------------------------------------------------------------
__global__ __launch_bounds__(256) void weights_kernel(const float* __restrict__ E,
                                                      const float* __restrict__ Wp) {
    const int t = threadIdx.x;
    const int kio = blockIdx.x * 256 + t;
    const int n0 = blockIdx.y * 128;
    __shared__ float Ws[EMB][256];
    __shared__ float Es[128][EMB];
#pragma unroll
    for (int d = 0; d < EMB; d++) Ws[d][t] = Wp[d * KIO + kio];
    for (int idx = t; idx < 128 * EMB; idx += 256)
        Es[idx >> 4][idx & 15] = E[(n0 + (idx >> 4)) * EMB + (idx & 15)];
    __syncthreads();
    for (int nn = 0; nn < 128; nn++) {
        float acc = 0.f;
#pragma unroll
        for (int d = 0; d < EMB; d++) acc += Es[nn][d] * Ws[d][t];
        g_w[(size_t)(n0 + nn) * KIO + kio] = acc;
    }
}

// K1b: bias[n,o] = sum_d E[n,d] * bp[d,o]
__global__ __launch_bounds__(256) void bias_kernel(const float* __restrict__ E,
                                                   const float* __restrict__ bp) {
    int idx = blockIdx.x * 256 + threadIdx.x;       // 65536
    int n = idx >> 6, o = idx & 63;
    float acc = 0.f;
#pragma unroll
    for (int d = 0; d < EMB; d++) acc += E[n * EMB + d] * bp[d * DOUT + o];
    g_bias[idx] = acc;
}

// ---------------------------------------------------------------------------
// K2: e[b,i,j] = exp(-sum_d |pa[b,i,d]-pa[b,j,d]|)
// grid (16 j-tiles of 64, 8 i-tiles of 128, 8 b)
// ---------------------------------------------------------------------------
__global__ __launch_bounds__(256) void e_kernel(const float* __restrict__ pa) {
    const int b = blockIdx.z;
    const int i0 = blockIdx.y * 128;
    const int j0 = blockIdx.x * 64;
    const int t = threadIdx.x;
    __shared__ float paI[128][17];
    __shared__ float paJ[64][17];
    const float* paB = pa + (size_t)b * NN * DPE;
    for (int idx = t; idx < 128 * 16; idx += 256)
        paI[idx >> 4][idx & 15] = paB[(i0 + (idx >> 4)) * DPE + (idx & 15)];
    for (int idx = t; idx < 64 * 16; idx += 256)
        paJ[idx >> 4][idx & 15] = paB[(j0 + (idx >> 4)) * DPE + (idx & 15)];
    __syncthreads();

    const int tj = t & 63, tig = t >> 6;
    float pj[16];
#pragma unroll
    for (int d = 0; d < 16; d++) pj[d] = paJ[tj][d];

    float* outBase = g_e + ((size_t)b * NN + i0) * NN + j0;
    for (int s = 0; s < 32; s++) {
        int i = tig * 32 + s;
        float acc = 0.f;
#pragma unroll
        for (int d = 0; d < 16; d++) acc += fabsf(paI[i][d] - pj[d]);
        outBase[(size_t)i * NN + tj] = __expf(-acc);
    }
}

// K3: Sinv[b,i] = 1 / sum_j e[b,i,j]   (row sum == column sum by symmetry)
__global__ __launch_bounds__(256) void rowsum_kernel() {
    int row = blockIdx.x * 8 + (threadIdx.x >> 5);   // 8192 rows
    int lane = threadIdx.x & 31;
    const float* r = g_e + (size_t)row * NN;
    float s = 0.f;
    for (int j = lane; j < NN; j += 32) s += r[j];
#pragma unroll
    for (int o = 16; o > 0; o >>= 1) s += __shfl_xor_sync(0xffffffffu, s, o);
    if (lane == 0) g_Sinv[row] = 1.0f / s;
}

// ---------------------------------------------------------------------------
// K4: sxT[m][b][d] = sum_c e[b,m,c] * (x[b,c,d] * Sinv[b,c])
// 64x64 tile GEMM, K-step 32.  grid (16 m-tiles, 8 b)
// ---------------------------------------------------------------------------
__global__ __launch_bounds__(256) void sx_kernel(const float* __restrict__ x) {
    const int b = blockIdx.y, m0 = blockIdx.x * 64;
    const int t = threadIdx.x;
    const int tm = t >> 4, td = t & 15;
    __shared__ float aS[64][33];
    __shared__ float bS[32][64];
    float acc[4][4] = {};
    const float* eB = g_e + ((size_t)b * NN + m0) * NN;
    const float* xB = x + (size_t)b * NN * DIN;
    const float* sI = g_Sinv + b * NN;

    for (int c0 = 0; c0 < NN; c0 += 32) {
        __syncthreads();
#pragma unroll
        for (int l = 0; l < 8; l++) {
            int idx = t + l * 256;
            int r = idx >> 5, c = idx & 31;
            aS[r][c] = eB[(size_t)r * NN + c0 + c];
        }
#pragma unroll
        for (int l = 0; l < 8; l++) {
            int idx = t + l * 256;
            int r = idx >> 6, d = idx & 63;
            bS[r][d] = xB[(c0 + r) * DIN + d] * sI[c0 + r];
        }
        __syncthreads();
#pragma unroll 8
        for (int kk = 0; kk < 32; kk++) {
            float a0 = aS[tm * 4 + 0][kk], a1 = aS[tm * 4 + 1][kk];
            float a2 = aS[tm * 4 + 2][kk], a3 = aS[tm * 4 + 3][kk];
            float4 bv = *reinterpret_cast<const float4*>(&bS[kk][td * 4]);
            acc[0][0] += a0 * bv.x; acc[0][1] += a0 * bv.y; acc[0][2] += a0 * bv.z; acc[0][3] += a0 * bv.w;
            acc[1][0] += a1 * bv.x; acc[1][1] += a1 * bv.y; acc[1][2] += a1 * bv.z; acc[1][3] += a1 * bv.w;
            acc[2][0] += a2 * bv.x; acc[2][1] += a2 * bv.y; acc[2][2] += a2 * bv.z; acc[2][3] += a2 * bv.w;
            acc[3][0] += a3 * bv.x; acc[3][1] += a3 * bv.y; acc[3][2] += a3 * bv.z; acc[3][3] += a3 * bv.w;
        }
    }
#pragma unroll
    for (int mi = 0; mi < 4; mi++) {
        float4 v = make_float4(acc[mi][0], acc[mi][1], acc[mi][2], acc[mi][3]);
        *reinterpret_cast<float4*>(&g_sxT[((size_t)(m0 + tm * 4 + mi) * BB + b) * DIN + td * 4]) = v;
    }
}

// ---------------------------------------------------------------------------
// K5: s1[n][bd] = sum_m sim[n,m] * sxT[m][bd]   (single 1024x512x1024 GEMM)
// grid (16 n-tiles, 8 bd-tiles)
// ---------------------------------------------------------------------------
__global__ __launch_bounds__(256) void s1_kernel() {
    const int n0 = blockIdx.x * 64, bd0 = blockIdx.y * 64;
    const int t = threadIdx.x;
    const int tm = t >> 4, td = t & 15;
    __shared__ float aS[64][33];
    __shared__ float bS[32][64];
    float acc[4][4] = {};

    for (int c0 = 0; c0 < NN; c0 += 32) {
        __syncthreads();
#pragma unroll
        for (int l = 0; l < 8; l++) {
            int idx = t + l * 256;
            int r = idx >> 5, c = idx & 31;
            aS[r][c] = g_sim[(size_t)(n0 + r) * NN + c0 + c];
        }
#pragma unroll
        for (int l = 0; l < 8; l++) {
            int idx = t + l * 256;
            int r = idx >> 6, d = idx & 63;
            bS[r][d] = g_sxT[(size_t)(c0 + r) * (BB * DIN) + bd0 + d];
        }
        __syncthreads();
#pragma unroll 8
        for (int kk = 0; kk < 32; kk++) {
            float a0 = aS[tm * 4 + 0][kk], a1 = aS[tm * 4 + 1][kk];
            float a2 = aS[tm * 4 + 2][kk], a3 = aS[tm * 4 + 3][kk];
            float4 bv = *reinterpret_cast<const float4*>(&bS[kk][td * 4]);
            acc[0][0] += a0 * bv.x; acc[0][1] += a0 * bv.y; acc[0][2] += a0 * bv.z; acc[0][3] += a0 * bv.w;
            acc[1][0] += a1 * bv.x; acc[1][1] += a1 * bv.y; acc[1][2] += a1 * bv.z; acc[1][3] += a1 * bv.w;
            acc[2][0] += a2 * bv.x; acc[2][1] += a2 * bv.y; acc[2][2] += a2 * bv.z; acc[2][3] += a2 * bv.w;
            acc[3][0] += a3 * bv.x; acc[3][1] += a3 * bv.y; acc[3][2] += a3 * bv.z; acc[3][3] += a3 * bv.w;
        }
    }
#pragma unroll
    for (int mi = 0; mi < 4; mi++) {
        float4 v = make_float4(acc[mi][0], acc[mi][1], acc[mi][2], acc[mi][3]);
        *reinterpret_cast<float4*>(&g_s1[(size_t)(n0 + tm * 4 + mi) * (BB * DIN) + bd0 + td * 4]) = v;
    }
}

// ---------------------------------------------------------------------------
// K6: out[b,n,o] = bias[n,o] + sum_i sx[n,b,i] w[n,0,i,o] + sum_i s1[n,b,i] w[n,1,i,o]
// one block per n; weights tile resident in smem
// ---------------------------------------------------------------------------
__global__ __launch_bounds__(256) void out_kernel(float* __restrict__ out) {
    const int n = blockIdx.x, t = threadIdx.x;
    __shared__ float wS[KIO];          // 32 KB
    __shared__ float xgS[2][BB][DIN];  // 4 KB
    __shared__ float bS[DOUT];
    const float* wp = g_w + (size_t)n * KIO;
    for (int idx = t; idx < KIO; idx += 256) wS[idx] = wp[idx];
    for (int idx = t; idx < BB * DIN; idx += 256) {
        xgS[0][idx >> 6][idx & 63] = g_sxT[(size_t)n * (BB * DIN) + idx];
        xgS[1][idx >> 6][idx & 63] = g_s1[(size_t)n * (BB * DIN) + idx];
    }
    if (t < DOUT) bS[t] = g_bias[n * DOUT + t];
    __syncthreads();

#pragma unroll
    for (int r = 0; r < 2; r++) {
        int idx = t + r * 256;
        int b = idx >> 6, o = idx & 63;
        float acc = bS[o];
#pragma unroll
        for (int i = 0; i < DIN; i++) acc += xgS[0][b][i] * wS[i * 64 + o];
#pragma unroll
        for (int i = 0; i < DIN; i++) acc += xgS[1][b][i] * wS[4096 + i * 64 + o];
        out[((size_t)b * NN + n) * DOUT + o] = acc;
    }
}

// ---------------------------------------------------------------------------
extern "C" void kernel_launch(void* const* d_in, const int* in_sizes, int n_in,
                              void* d_out, int out_size) {
    const float* x    = (const float*)d_in[0];   // [8,1024,64]
    const float* E    = (const float*)d_in[1];   // [1024,16]
    const float* pa   = (const float*)d_in[2];   // [8,1024,16]
    const float* Wp   = (const float*)d_in[3];   // [16,2,64,64]
    const float* bp   = (const float*)d_in[4];   // [16,64]
    float* out = (float*)d_out;                  // [8,1024,64]

    sim_kernel<<<NN, 256>>>(E);
    weights_kernel<<<dim3(KIO / 256, NN / 128), 256>>>(E, Wp);
    bias_kernel<<<NN * DOUT / 256, 256>>>(E, bp);
    e_kernel<<<dim3(NN / 64, NN / 128, BB), 256>>>(pa);
    rowsum_kernel<<<BB * NN / 8, 256>>>();
    sx_kernel<<<dim3(NN / 64, BB), 256>>>(x);
    s1_kernel<<<dim3(NN / 64, BB * DIN / 64), 256>>>();
    out_kernel<<<NN, 256>>>(out);
}

// round 3
// speedup vs baseline: 1.0114x; 1.0114x over previous
#include <cuda_runtime.h>

#define NN 1024
#define BB 8
#define DIN 64
#define DOUT 64
#define EMB 16
#define DPE 16
#define KIO 8192   // 2*64*64

// ---- device scratch (no allocations allowed) ----
__device__ float g_sim[NN * NN];          // 4 MB
__device__ float g_w[NN * KIO];           // 32 MB  weights[n][k][i][o]
__device__ float g_bias[NN * DOUT];       // 256 KB
__device__ float g_e[BB * NN * NN];       // 32 MB  exp(-d1), symmetric per b
__device__ float g_Sinv[BB * NN];         // 32 KB
__device__ float g_sxT[NN * BB * DIN];    // 2 MB   sx as [m][b][d]
__device__ float g_s1[NN * BB * DIN];     // 2 MB   sim@sx as [n][b][d]

// ---------------------------------------------------------------------------
// K0: sim = softmax(relu(E E^T), axis=1)   one block per row
// ---------------------------------------------------------------------------
__global__ __launch_bounds__(256) void sim_kernel(const float* __restrict__ E) {
    const int i = blockIdx.x;
    const int t = threadIdx.x;
    __shared__ float Ei[EMB];
    __shared__ float red[256];
    if (t < EMB) Ei[t] = E[i * EMB + t];
    __syncthreads();

    float v[4];
    float mx = -1e30f;
#pragma unroll
    for (int r = 0; r < 4; r++) {
        int j = t + r * 256;
        const float4* Ej = reinterpret_cast<const float4*>(E + j * EMB);
        float acc = 0.f;
#pragma unroll
        for (int q = 0; q < 4; q++) {
            float4 e4 = Ej[q];
            acc += Ei[q * 4 + 0] * e4.x + Ei[q * 4 + 1] * e4.y
                 + Ei[q * 4 + 2] * e4.z + Ei[q * 4 + 3] * e4.w;
        }
        acc = fmaxf(acc, 0.f);
        v[r] = acc;
        mx = fmaxf(mx, acc);
    }
    red[t] = mx; __syncthreads();
    for (int s = 128; s > 0; s >>= 1) { if (t < s) red[t] = fmaxf(red[t], red[t + s]); __syncthreads(); }
    mx = red[0]; __syncthreads();

    float sum = 0.f;
#pragma unroll
    for (int r = 0; r < 4; r++) { v[r] = __expf(v[r] - mx); sum += v[r]; }
    red[t] = sum; __syncthreads();
    for (int s = 128; s > 0; s >>= 1) { if (t < s) red[t] += red[t + s]; __syncthreads(); }
    float inv = 1.0f / red[0];
#pragma unroll
    for (int r = 0; r < 4; r++) g_sim[i * NN + t + r * 256] = v[r] * inv;
}

// ---------------------------------------------------------------------------
// K1: weights[n, kio] = sum_d E[n,d] * Wp[d, kio]
// grid (32 kio-tiles of 256, 8 n-chunks of 128)
// ---------------------------------------------------------------------------
__global__ __launch_bounds__(256) void weights_kernel(const float* __restrict__ E,
                                                      const float* __restrict__ Wp) {
    const int t = threadIdx.x;
    const int kio = blockIdx.x * 256 + t;
    const int n0 = blockIdx.y * 128;
    __shared__ float Ws[EMB][256];
    __shared__ float Es[128][EMB];
#pragma unroll
    for (int d = 0; d < EMB; d++) Ws[d][t] = Wp[d * KIO + kio];
    for (int idx = t; idx < 128 * EMB; idx += 256)
        Es[idx >> 4][idx & 15] = E[(n0 + (idx >> 4)) * EMB + (idx & 15)];
    __syncthreads();
    for (int nn = 0; nn < 128; nn++) {
        float acc = 0.f;
#pragma unroll
        for (int d = 0; d < EMB; d++) acc += Es[nn][d] * Ws[d][t];
        g_w[(size_t)(n0 + nn) * KIO + kio] = acc;
    }
}

// K1b: bias[n,o] = sum_d E[n,d] * bp[d,o]
__global__ __launch_bounds__(256) void bias_kernel(const float* __restrict__ E,
                                                   const float* __restrict__ bp) {
    int idx = blockIdx.x * 256 + threadIdx.x;       // 65536
    int n = idx >> 6, o = idx & 63;
    float acc = 0.f;
#pragma unroll
    for (int d = 0; d < EMB; d++) acc += E[n * EMB + d] * bp[d * DOUT + o];
    g_bias[idx] = acc;
}

// ---------------------------------------------------------------------------
// K2: e[b,i,j] = exp(-sum_d |pa[b,i,d]-pa[b,j,d]|)
// grid (16 j-tiles of 64, 8 i-tiles of 128, 8 b)
// ---------------------------------------------------------------------------
__global__ __launch_bounds__(256) void e_kernel(const float* __restrict__ pa) {
    const int b = blockIdx.z;
    const int i0 = blockIdx.y * 128;
    const int j0 = blockIdx.x * 64;
    const int t = threadIdx.x;
    __shared__ float paI[128][17];
    __shared__ float paJ[64][17];
    const float* paB = pa + (size_t)b * NN * DPE;
    for (int idx = t; idx < 128 * 16; idx += 256)
        paI[idx >> 4][idx & 15] = paB[(i0 + (idx >> 4)) * DPE + (idx & 15)];
    for (int idx = t; idx < 64 * 16; idx += 256)
        paJ[idx >> 4][idx & 15] = paB[(j0 + (idx >> 4)) * DPE + (idx & 15)];
    __syncthreads();

    const int tj = t & 63, tig = t >> 6;
    float pj[16];
#pragma unroll
    for (int d = 0; d < 16; d++) pj[d] = paJ[tj][d];

    float* outBase = g_e + ((size_t)b * NN + i0) * NN + j0;
    for (int s = 0; s < 32; s++) {
        int i = tig * 32 + s;
        float acc = 0.f;
#pragma unroll
        for (int d = 0; d < 16; d++) acc += fabsf(paI[i][d] - pj[d]);
        outBase[(size_t)i * NN + tj] = __expf(-acc);
    }
}

// K3: Sinv[b,i] = 1 / sum_j e[b,i,j]   (row sum == column sum by symmetry)
__global__ __launch_bounds__(256) void rowsum_kernel() {
    int row = blockIdx.x * 8 + (threadIdx.x >> 5);   // 8192 rows
    int lane = threadIdx.x & 31;
    const float* r = g_e + (size_t)row * NN;
    float s = 0.f;
    for (int j = lane; j < NN; j += 32) s += r[j];
#pragma unroll
    for (int o = 16; o > 0; o >>= 1) s += __shfl_xor_sync(0xffffffffu, s, o);
    if (lane == 0) g_Sinv[row] = 1.0f / s;
}

// ---------------------------------------------------------------------------
// K4: sxT[m][b][d] = sum_c e[b,m,c] * (x[b,c,d] * Sinv[b,c])
// 64x64 tile GEMM, K-step 32.  grid (16 m-tiles, 8 b)
// ---------------------------------------------------------------------------
__global__ __launch_bounds__(256) void sx_kernel(const float* __restrict__ x) {
    const int b = blockIdx.y, m0 = blockIdx.x * 64;
    const int t = threadIdx.x;
    const int tm = t >> 4, td = t & 15;
    __shared__ float aS[64][33];
    __shared__ float bS[32][64];
    float acc[4][4] = {};
    const float* eB = g_e + ((size_t)b * NN + m0) * NN;
    const float* xB = x + (size_t)b * NN * DIN;
    const float* sI = g_Sinv + b * NN;

    for (int c0 = 0; c0 < NN; c0 += 32) {
        __syncthreads();
#pragma unroll
        for (int l = 0; l < 8; l++) {
            int idx = t + l * 256;
            int r = idx >> 5, c = idx & 31;
            aS[r][c] = eB[(size_t)r * NN + c0 + c];
        }
#pragma unroll
        for (int l = 0; l < 8; l++) {
            int idx = t + l * 256;
            int r = idx >> 6, d = idx & 63;
            bS[r][d] = xB[(c0 + r) * DIN + d] * sI[c0 + r];
        }
        __syncthreads();
#pragma unroll 8
        for (int kk = 0; kk < 32; kk++) {
            float a0 = aS[tm * 4 + 0][kk], a1 = aS[tm * 4 + 1][kk];
            float a2 = aS[tm * 4 + 2][kk], a3 = aS[tm * 4 + 3][kk];
            float4 bv = *reinterpret_cast<const float4*>(&bS[kk][td * 4]);
            acc[0][0] += a0 * bv.x; acc[0][1] += a0 * bv.y; acc[0][2] += a0 * bv.z; acc[0][3] += a0 * bv.w;
            acc[1][0] += a1 * bv.x; acc[1][1] += a1 * bv.y; acc[1][2] += a1 * bv.z; acc[1][3] += a1 * bv.w;
            acc[2][0] += a2 * bv.x; acc[2][1] += a2 * bv.y; acc[2][2] += a2 * bv.z; acc[2][3] += a2 * bv.w;
            acc[3][0] += a3 * bv.x; acc[3][1] += a3 * bv.y; acc[3][2] += a3 * bv.z; acc[3][3] += a3 * bv.w;
        }
    }
#pragma unroll
    for (int mi = 0; mi < 4; mi++) {
        float4 v = make_float4(acc[mi][0], acc[mi][1], acc[mi][2], acc[mi][3]);
        *reinterpret_cast<float4*>(&g_sxT[((size_t)(m0 + tm * 4 + mi) * BB + b) * DIN + td * 4]) = v;
    }
}

// ---------------------------------------------------------------------------
// K5: s1[n][bd] = sum_m sim[n,m] * sxT[m][bd]   (single 1024x512x1024 GEMM)
// grid (16 n-tiles, 8 bd-tiles)
// ---------------------------------------------------------------------------
__global__ __launch_bounds__(256) void s1_kernel() {
    const int n0 = blockIdx.x * 64, bd0 = blockIdx.y * 64;
    const int t = threadIdx.x;
    const int tm = t >> 4, td = t & 15;
    __shared__ float aS[64][33];
    __shared__ float bS[32][64];
    float acc[4][4] = {};

    for (int c0 = 0; c0 < NN; c0 += 32) {
        __syncthreads();
#pragma unroll
        for (int l = 0; l < 8; l++) {
            int idx = t + l * 256;
            int r = idx >> 5, c = idx & 31;
            aS[r][c] = g_sim[(size_t)(n0 + r) * NN + c0 + c];
        }
#pragma unroll
        for (int l = 0; l < 8; l++) {
            int idx = t + l * 256;
            int r = idx >> 6, d = idx & 63;
            bS[r][d] = g_sxT[(size_t)(c0 + r) * (BB * DIN) + bd0 + d];
        }
        __syncthreads();
#pragma unroll 8
        for (int kk = 0; kk < 32; kk++) {
            float a0 = aS[tm * 4 + 0][kk], a1 = aS[tm * 4 + 1][kk];
            float a2 = aS[tm * 4 + 2][kk], a3 = aS[tm * 4 + 3][kk];
            float4 bv = *reinterpret_cast<const float4*>(&bS[kk][td * 4]);
            acc[0][0] += a0 * bv.x; acc[0][1] += a0 * bv.y; acc[0][2] += a0 * bv.z; acc[0][3] += a0 * bv.w;
            acc[1][0] += a1 * bv.x; acc[1][1] += a1 * bv.y; acc[1][2] += a1 * bv.z; acc[1][3] += a1 * bv.w;
            acc[2][0] += a2 * bv.x; acc[2][1] += a2 * bv.y; acc[2][2] += a2 * bv.z; acc[2][3] += a2 * bv.w;
            acc[3][0] += a3 * bv.x; acc[3][1] += a3 * bv.y; acc[3][2] += a3 * bv.z; acc[3][3] += a3 * bv.w;
        }
    }
#pragma unroll
    for (int mi = 0; mi < 4; mi++) {
        float4 v = make_float4(acc[mi][0], acc[mi][1], acc[mi][2], acc[mi][3]);
        *reinterpret_cast<float4*>(&g_s1[(size_t)(n0 + tm * 4 + mi) * (BB * DIN) + bd0 + td * 4]) = v;
    }
}

// ---------------------------------------------------------------------------
// K6: out[b,n,o] = bias[n,o] + sum_i sx[n,b,i] w[n,0,i,o] + sum_i s1[n,b,i] w[n,1,i,o]
// one block per n; weights tile resident in smem
// ---------------------------------------------------------------------------
__global__ __launch_bounds__(256) void out_kernel(float* __restrict__ out) {
    const int n = blockIdx.x, t = threadIdx.x;
    __shared__ float wS[KIO];          // 32 KB
    __shared__ float xgS[2][BB][DIN];  // 4 KB
    __shared__ float bS[DOUT];
    const float* wp = g_w + (size_t)n * KIO;
    for (int idx = t; idx < KIO; idx += 256) wS[idx] = wp[idx];
    for (int idx = t; idx < BB * DIN; idx += 256) {
        xgS[0][idx >> 6][idx & 63] = g_sxT[(size_t)n * (BB * DIN) + idx];
        xgS[1][idx >> 6][idx & 63] = g_s1[(size_t)n * (BB * DIN) + idx];
    }
    if (t < DOUT) bS[t] = g_bias[n * DOUT + t];
    __syncthreads();

#pragma unroll
    for (int r = 0; r < 2; r++) {
        int idx = t + r * 256;
        int b = idx >> 6, o = idx & 63;
        float acc = bS[o];
#pragma unroll
        for (int i = 0; i < DIN; i++) acc += xgS[0][b][i] * wS[i * 64 + o];
#pragma unroll
        for (int i = 0; i < DIN; i++) acc += xgS[1][b][i] * wS[4096 + i * 64 + o];
        out[((size_t)b * NN + n) * DOUT + o] = acc;
    }
}

// ---------------------------------------------------------------------------
extern "C" void kernel_launch(void* const* d_in, const int* in_sizes, int n_in,
                              void* d_out, int out_size) {
    const float* x    = (const float*)d_in[0];   // [8,1024,64]
    const float* E    = (const float*)d_in[1];   // [1024,16]
    const float* pa   = (const float*)d_in[2];   // [8,1024,16]
    const float* Wp   = (const float*)d_in[3];   // [16,2,64,64]
    const float* bp   = (const float*)d_in[4];   // [16,64]
    float* out = (float*)d_out;                  // [8,1024,64]

    sim_kernel<<<NN, 256>>>(E);
    weights_kernel<<<dim3(KIO / 256, NN / 128), 256>>>(E, Wp);
    bias_kernel<<<NN * DOUT / 256, 256>>>(E, bp);
    e_kernel<<<dim3(NN / 64, NN / 128, BB), 256>>>(pa);
    rowsum_kernel<<<BB * NN / 8, 256>>>();
    sx_kernel<<<dim3(NN / 64, BB), 256>>>(x);
    s1_kernel<<<dim3(NN / 64, BB * DIN / 64), 256>>>();
    out_kernel<<<NN, 256>>>(out);
}